// round 2
// baseline (speedup 1.0000x reference)
#include <cuda_runtime.h>
#include <math.h>

// Problem constants
#define HW      262144        // 512*512
#define NTILES  16384         // 2M pixels / 128-pixel tiles
#define GRID1   296           // 2 * 148 SMs
#define K       19
#define KC      1216          // 19*64

// Scratch (no allocation allowed -> __device__ globals)
__device__ float g_psums[GRID1 * KC];
__device__ int   g_pcnts[GRID1 * K];
__device__ float g_sums[KC];
__device__ int   g_shift;     // 0: targets int32, 1: targets int64 (read low word)

// Dynamic smem layout (floats): tile[64*128] | acc[8*1216] | labels(int)[128] | cnt(int)[19]
#define TILE_F   8192
#define ACC_F    (8*1216)
#define SMEM_BYTES ((TILE_F + ACC_F)*4 + 128*4 + 19*4 + 32)

// ---------------------------------------------------------------------------
// K0: detect targets dtype. int64 labels (0..18) have zero high words at all
// odd int32 indices; int32 random labels make that pattern ~impossible.
// ---------------------------------------------------------------------------
__global__ void k0_detect(const int* __restrict__ t32) {
    int all0 = 1;
    #pragma unroll
    for (int i = 0; i < 32; ++i)
        if (t32[2 * i + 1] != 0) all0 = 0;
    g_shift = all0;
}

// ---------------------------------------------------------------------------
// K1: streaming centroid scatter-sum.
// Tile = 128 pixels x 64 channels. Per tile:
//   prefetch (4x LDG.128/thread, coalesced) issued during previous tile's
//   accumulate -> STS.128 into XOR-swizzled transpose tile -> accumulate:
//   lanes span channels (label uniform per pixel-quad group), non-atomic RMW
//   into per-group private accumulators (exclusive (g,c) owner).
// ---------------------------------------------------------------------------
__global__ __launch_bounds__(512) void k1_kernel(const float* __restrict__ inp,
                                                 const int* __restrict__ tgt32) {
    extern __shared__ float sm[];
    float* tile   = sm;
    float* acc    = sm + TILE_F;
    int*   labels = (int*)(sm + TILE_F + ACC_F);
    int*   cnt    = labels + 128;
    const int tid = threadIdx.x;
    const int shift = g_shift;

    // zero accumulators + counts
    for (int i = tid; i < ACC_F; i += 512) acc[i] = 0.f;
    if (tid < K) cnt[tid] = 0;

    // load-phase mapping: q = pixel-quad (0..31), channels w, 16+w, 32+w, 48+w
    const int q = tid & 31, w = tid >> 5;
    const int c0 = w, c1 = 16 + w, c2 = 32 + w, c3 = 48 + w;
    // accumulate-phase mapping: channel ca, pixel-group g (8 groups of 64 thr)
    const int ca = tid & 63, g = tid >> 6, sw = ca & 31;

    int t = blockIdx.x;
    float4 v0, v1, v2, v3;
    int lab = 0;
    {   // prefetch tile t
        const int b = t >> 11, hw0 = (t & 2047) << 7;
        const float* p = inp + ((size_t)b << 24) + hw0 + (q << 2);
        v0 = __ldcs((const float4*)(p + (size_t)c0 * HW));
        v1 = __ldcs((const float4*)(p + (size_t)c1 * HW));
        v2 = __ldcs((const float4*)(p + (size_t)c2 * HW));
        v3 = __ldcs((const float4*)(p + (size_t)c3 * HW));
        if (tid < 128) lab = __ldcs(tgt32 + ((size_t)((b << 18) + hw0 + tid) << shift));
    }

    while (true) {
        __syncthreads();   // previous accumulate done -> tile/labels reusable
        // store phase: XOR-swizzled, conflict-free STS.128
        *(float4*)(tile + c0*128 + ((q ^ (c0 & 31)) << 2)) = v0;
        *(float4*)(tile + c1*128 + ((q ^ (c1 & 31)) << 2)) = v1;
        *(float4*)(tile + c2*128 + ((q ^ (c2 & 31)) << 2)) = v2;
        *(float4*)(tile + c3*128 + ((q ^ (c3 & 31)) << 2)) = v3;
        if (tid < 128) {
            int l = min(max(lab, 0), K - 1);   // crash-proof; mismatch -> rel_err signal
            labels[tid] = l;
            atomicAdd(&cnt[l], 1);
        }
        __syncthreads();

        const int nt = t + GRID1;
        if (nt < NTILES) {   // prefetch next tile: LDG latency hides behind accumulate
            const int b = nt >> 11, hw0 = (nt & 2047) << 7;
            const float* p = inp + ((size_t)b << 24) + hw0 + (q << 2);
            v0 = __ldcs((const float4*)(p + (size_t)c0 * HW));
            v1 = __ldcs((const float4*)(p + (size_t)c1 * HW));
            v2 = __ldcs((const float4*)(p + (size_t)c2 * HW));
            v3 = __ldcs((const float4*)(p + (size_t)c3 * HW));
            if (tid < 128) lab = __ldcs(tgt32 + ((size_t)((b << 18) + hw0 + tid) << shift));
        }

        // accumulate phase: group g handles quads {g, g+8, g+16, g+24};
        // all 64 threads of a group share one pixel-quad -> labels uniform ->
        // thread exclusively owns acc[g][*][ca] -> plain RMW, no atomics.
        {
            const float* trow = tile + ca * 128;
            float* arow = acc + g * 1216 + ca;
            #pragma unroll
            for (int i = 0; i < 4; ++i) {
                const int qq = g + (i << 3);
                float4 x = *(const float4*)(trow + ((qq ^ sw) << 2));
                int4 lb = *(const int4*)(labels + (qq << 2));   // warp broadcast
                arow[lb.x * 64] += x.x;
                arow[lb.y * 64] += x.y;
                arow[lb.z * 64] += x.z;
                arow[lb.w * 64] += x.w;
            }
        }
        if (nt >= NTILES) break;
        t = nt;
    }

    __syncthreads();
    // merge 8 group copies -> per-block partial (deterministic)
    for (int i = tid; i < KC; i += 512) {
        float s = 0.f;
        #pragma unroll
        for (int gg = 0; gg < 8; ++gg) s += acc[gg * 1216 + i];
        g_psums[blockIdx.x * KC + i] = s;
    }
    if (tid < K) g_pcnts[blockIdx.x * K + tid] = cnt[tid];
}

// ---------------------------------------------------------------------------
// K2: reduce 296 block-partials -> g_sums[1216]. 38 blocks x 256 threads,
// each block owns 32 outputs, 8-way split over partials + shared tree.
// ---------------------------------------------------------------------------
__global__ void k2_kernel() {
    __shared__ float red[256];
    const int tid = threadIdx.x;
    const int o = (blockIdx.x << 5) + (tid & 31);
    const int s = tid >> 5;
    float sum = 0.f;
    const int p0 = s * 37;                 // 296 = 8*37
    #pragma unroll 4
    for (int p = p0; p < p0 + 37; ++p) sum += g_psums[p * KC + o];
    red[tid] = sum;
    __syncthreads();
    if (tid < 128) red[tid] += red[tid + 128];
    __syncthreads();
    if (tid < 64) red[tid] += red[tid + 64];
    __syncthreads();
    if (tid < 32) g_sums[o] = red[tid] + red[tid + 32];
}

// ---------------------------------------------------------------------------
// K3: counts reduce + centroids + cosine-embedding loss. 1 block.
// ---------------------------------------------------------------------------
__global__ __launch_bounds__(512) void k3_kernel(float* __restrict__ out) {
    __shared__ float cen[KC];
    __shared__ float nrm[K];
    __shared__ int   cnts[K];
    __shared__ float red[512];
    const int tid = threadIdx.x;

    if (tid < K) {
        int s = 0;
        #pragma unroll 8
        for (int p = 0; p < GRID1; ++p) s += g_pcnts[p * K + tid];
        cnts[tid] = s;
    }
    __syncthreads();
    for (int i = tid; i < KC; i += 512)
        cen[i] = g_sums[i] / fmaxf((float)cnts[i >> 6], 1.0f);
    __syncthreads();
    if (tid < K) {
        float nn = 0.f;
        #pragma unroll
        for (int c = 0; c < 64; ++c) { float v = cen[(tid << 6) + c]; nn += v * v; }
        nrm[tid] = fmaxf(sqrtf(nn), 1e-8f);
    }
    __syncthreads();
    for (int i = tid; i < KC; i += 512)
        cen[i] = cen[i] / nrm[i >> 6];
    __syncthreads();

    float val = 0.f;
    if (tid < K * K) {
        const int k1i = tid / K, k2i = tid % K;
        float dot = 0.f;
        #pragma unroll
        for (int c = 0; c < 64; ++c)
            dot += cen[(k1i << 6) + c] * cen[(k2i << 6) + c];
        val = (k1i == k2i) ? (1.0f - dot) : fmaxf(dot, 0.0f);
    }
    red[tid] = val;
    __syncthreads();
    #pragma unroll
    for (int off = 256; off > 0; off >>= 1) {
        if (tid < off) red[tid] += red[tid + off];
        __syncthreads();
    }
    if (tid == 0) out[0] = red[0] / 6859.0f;   // K^3
}

// ---------------------------------------------------------------------------
extern "C" void kernel_launch(void* const* d_in, const int* in_sizes, int n_in,
                              void* d_out, int out_size) {
    // Select pointers by element count (inputs: 134M, targets: 2M) — robust to order.
    int ii = 0, ti = 1;
    if (n_in >= 2 && in_sizes[1] > in_sizes[0]) { ii = 1; ti = 0; }
    const float* inp = (const float*)d_in[ii];
    const int* tgt32 = (const int*)d_in[ti];
    cudaFuncSetAttribute(k1_kernel, cudaFuncAttributeMaxDynamicSharedMemorySize, SMEM_BYTES);
    k0_detect<<<1, 1>>>(tgt32);
    k1_kernel<<<GRID1, 512, SMEM_BYTES>>>(inp, tgt32);
    k2_kernel<<<38, 256>>>();
    k3_kernel<<<1, 512>>>((float*)d_out);
}